// round 2
// baseline (speedup 1.0000x reference)
#include <cuda_runtime.h>
#include <cstdint>

#define FULL 0xffffffffu

constexpr int   NTAG   = 32;
constexpr int   RING   = 8;          // smem ring depth in steps
constexpr int   STEPF  = NTAG * NTAG; // 1024 floats per step (4 KB)
constexpr float NEGINF = -1e4f;

__device__ __forceinline__ void cp16(uint32_t dst, const void* src) {
    asm volatile("cp.async.cg.shared.global [%0], [%1], 16;" :: "r"(dst), "l"(src) : "memory");
}
__device__ __forceinline__ void cp_commit() {
    asm volatile("cp.async.commit_group;" ::: "memory");
}
template<int N> __device__ __forceinline__ void cp_wait() {
    asm volatile("cp.async.wait_group %0;" :: "n"(N) : "memory");
}

// bool-array accessor: mode 0 = int32, 1 = uint8, 2 = float32
__device__ __forceinline__ bool getb(const void* p, int idx, int mode) {
    if (mode == 0) return ((const int*)p)[idx] != 0;
    if (mode == 1) return ((const uint8_t*)p)[idx] != 0;
    return ((const float*)p)[idx] != 0.0f;
}

// One Viterbi step for lane j: best/first-argmax over i of alpha[i] + ((phi[i][j]+tp[i]) [+ep]).
// Float op order replicates the reference exactly so ties/argmax match bitwise.
template<bool END>
__device__ __forceinline__ void vstep(const float* __restrict__ ph, const float* tp,
                                      float my_alpha, float epj, float& best, int& bidx)
{
    float s[NTAG];
#pragma unroll
    for (int i = 0; i < NTAG; ++i) {
        float av = __shfl_sync(FULL, my_alpha, i);
        float e  = ph[i * NTAG] + tp[i];
        if (END) e += epj;
        s[i] = av + e;
    }
    // left-biased select tree: value = max, index = first (smallest i) max
    float v[16]; int ix[16];
#pragma unroll
    for (int k = 0; k < 16; ++k) {
        bool c = s[2*k+1] > s[2*k];
        v[k] = c ? s[2*k+1] : s[2*k];  ix[k] = c ? 2*k+1 : 2*k;
    }
#pragma unroll
    for (int k = 0; k < 8; ++k) {
        bool c = v[2*k+1] > v[2*k];
        v[k] = c ? v[2*k+1] : v[2*k];  ix[k] = c ? ix[2*k+1] : ix[2*k];
    }
#pragma unroll
    for (int k = 0; k < 4; ++k) {
        bool c = v[2*k+1] > v[2*k];
        v[k] = c ? v[2*k+1] : v[2*k];  ix[k] = c ? ix[2*k+1] : ix[2*k];
    }
#pragma unroll
    for (int k = 0; k < 2; ++k) {
        bool c = v[2*k+1] > v[2*k];
        v[k] = c ? v[2*k+1] : v[2*k];  ix[k] = c ? ix[2*k+1] : ix[2*k];
    }
    bool c = v[1] > v[0];
    best = c ? v[1] : v[0];
    bidx = c ? ix[1] : ix[0];
}

__global__ void __launch_bounds__(32, 1)
ConstrainedDecoder_kernel(const float* __restrict__ lp,
                          const void* __restrict__ mask,
                          const void* __restrict__ startc,
                          const void* __restrict__ endc,
                          const void* __restrict__ transc,
                          float* __restrict__ out,
                          int B, int T)
{
    extern __shared__ char smem[];
    float*   buf  = (float*)smem;                           // RING*1024 floats = 32 KB
    uint8_t* back = (uint8_t*)(smem + RING * STEPF * 4);    // T*32 bytes

    const int b = blockIdx.x;
    const int j = threadIdx.x;

    // ---- detect bool encoding from mask[0] (guaranteed true) ----
    uint32_t w0 = ((const uint32_t*)mask)[0];
    const int mode = (w0 == 1u) ? 0 : (w0 == 0x01010101u) ? 1 : 2;

    // ---- sequence length (mask prefix-true) ----
    int len = 0;
    {
        const size_t mbase = (size_t)b * T;
        for (int k = j; k < T; k += 32)
            if (getb(mask, (int)(mbase + k), mode)) len = k + 1;
#pragma unroll
        for (int off = 16; off; off >>= 1)
            len = max(len, __shfl_xor_sync(FULL, len, off));
    }
    if (len < 1) len = 1;
    if (len > T) len = T;

    // ---- constraint penalties ----
    const float sp = getb(startc, j, mode) ? 0.0f : NEGINF;
    const float ep = getb(endc,  j, mode) ? 0.0f : NEGINF;
    float tp[NTAG];
#pragma unroll
    for (int i = 0; i < NTAG; ++i)
        tp[i] = getb(transc, i * NTAG + j, mode) ? 0.0f : NEGINF;

    // ---- async copy pipeline ----
    const char* g = (const char*)(lp + (size_t)b * T * STEPF);
    const uint32_t sbase = (uint32_t)__cvta_generic_to_shared(buf);

#define ISSUE(t) do {                                                     \
        uint32_t _d = sbase + (uint32_t)(((t) & (RING - 1)) * 4096) + j * 16; \
        const char* _s = g + (size_t)(t) * 4096 + j * 16;                 \
        _Pragma("unroll")                                                 \
        for (int _k = 0; _k < 8; ++_k) cp16(_d + _k * 512, _s + _k * 512);\
        cp_commit();                                                      \
    } while (0)

    {
        int pre = (RING - 1) < len ? (RING - 1) : len;
        for (int t = 0; t < pre; ++t) ISSUE(t);
    }

    float my_alpha = 0.0f;
    const int lenm1 = len - 1;

#pragma unroll 1
    for (int t = 0; t < len; ++t) {
        if (len - t >= RING - 1) cp_wait<RING - 2>(); else cp_wait<0>();
        __syncwarp();
        const float* ph = buf + (size_t)(t & (RING - 1)) * STEPF + j;

        if (t == 0) {
            // alpha0[j] = max_i phi0[i][j] + sp[j] (+ ep[j] if len == 1)
            float m = ph[0];
#pragma unroll
            for (int i = 1; i < NTAG; ++i) m = fmaxf(m, ph[i * NTAG]);
            my_alpha = m + sp;
            if (len == 1) my_alpha += ep;
        } else {
            float best; int bi;
            if (t == lenm1) vstep<true >(ph, tp, my_alpha, ep, best, bi);
            else            vstep<false>(ph, tp, my_alpha, ep, best, bi);
            my_alpha = best;
            back[(size_t)t * NTAG + j] = (uint8_t)bi;
        }

        int nt = t + RING - 1;
        if (nt < len) ISSUE(nt);
    }
#undef ISSUE

    // ---- final max / first-argmax over tags ----
    __syncwarp();
    float v = my_alpha; int ix = j;
#pragma unroll
    for (int off = 16; off; off >>= 1) {
        float ov = __shfl_xor_sync(FULL, v, off);
        int   oi = __shfl_xor_sync(FULL, ix, off);
        if (ov > v || (ov == v && oi < ix)) { v = ov; ix = oi; }
    }

    float* out_mlp  = out;       // [B]
    float* out_tags = out + B;   // [B, T]
    if (j == 0) out_mlp[b] = v;

    // padding tags
    for (int k = len + j; k < T; k += 32)
        out_tags[(size_t)b * T + k] = -1.0f;

    // ---- backtrack (lane 0, sequential smem chain) ----
    if (j == 0) {
        int tag = ix;
        out_tags[(size_t)b * T + lenm1] = (float)tag;
        for (int tt = lenm1; tt >= 1; --tt) {
            tag = back[(size_t)tt * NTAG + tag];
            out_tags[(size_t)b * T + tt - 1] = (float)tag;
        }
    }
}

extern "C" void kernel_launch(void* const* d_in, const int* in_sizes, int n_in,
                              void* d_out, int out_size)
{
    const float* lp   = (const float*)d_in[0];
    const void*  mask = d_in[1];
    const void*  sc   = d_in[2];
    const void*  ec   = d_in[3];
    const void*  tc   = d_in[4];

    const int BT = in_sizes[1];      // B*T elements in mask
    int B = out_size - BT;           // out = [B] mlp + [B*T] tags
    if (B <= 0) B = 64;
    const int T = BT / B;

    size_t smem = (size_t)RING * STEPF * 4 + (size_t)T * NTAG;
    cudaFuncSetAttribute(ConstrainedDecoder_kernel,
                         cudaFuncAttributeMaxDynamicSharedMemorySize, (int)smem);

    ConstrainedDecoder_kernel<<<B, 32, smem>>>(lp, mask, sc, ec, tc,
                                               (float*)d_out, B, T);
}

// round 4
// speedup vs baseline: 1.5294x; 1.5294x over previous
#include <cuda_runtime.h>
#include <cstdint>

#define FULL 0xffffffffu

constexpr int   NTAG    = 32;
constexpr int   CH      = 8;              // steps per chunk
constexpr int   NS      = 4;              // ring slots (chunks)
constexpr int   D       = 2;              // chunks prefetched ahead
constexpr int   STEPF   = NTAG * NTAG;    // 1024 floats per step
constexpr int   CHUNK_B = CH * STEPF * 4; // 32768 bytes
constexpr float NEGINF  = -1e4f;

__device__ __forceinline__ void cp16(uint32_t dst, const void* src) {
    asm volatile("cp.async.cg.shared.global [%0], [%1], 16;" :: "r"(dst), "l"(src) : "memory");
}
__device__ __forceinline__ void cp_commit() {
    asm volatile("cp.async.commit_group;" ::: "memory");
}
template<int N> __device__ __forceinline__ void cp_wait() {
    asm volatile("cp.async.wait_group %0;" :: "n"(N) : "memory");
}
__device__ __forceinline__ void barsync() {
    asm volatile("bar.sync 0;" ::: "memory");
}

// bool-array accessor: mode 0 = int32, 1 = uint8, 2 = float32
__device__ __forceinline__ bool getb(const void* p, int idx, int mode) {
    if (mode == 0) return ((const int*)p)[idx] != 0;
    if (mode == 1) return ((const uint8_t*)p)[idx] != 0;
    return ((const float*)p)[idx] != 0.0f;
}

// One Viterbi step for lane j: best/first-argmax over i of alpha[i] + ((phi[i][j]+tp[i]) [+ep]).
// Float op order replicates the reference exactly so argmax ties match bitwise.
template<bool END>
__device__ __forceinline__ void vstep(const float* __restrict__ ph, const float* tp,
                                      float my_alpha, float epj, float& best, int& bidx)
{
    float s[NTAG];
#pragma unroll
    for (int i = 0; i < NTAG; ++i) {
        float av = __shfl_sync(FULL, my_alpha, i);
        float e  = ph[i * NTAG] + tp[i];
        if (END) e += epj;
        s[i] = av + e;
    }
    // left-biased select tree: value = max, index = first (smallest i) max
    float v[16]; int ix[16];
#pragma unroll
    for (int k = 0; k < 16; ++k) {
        bool c = s[2*k+1] > s[2*k];
        v[k] = c ? s[2*k+1] : s[2*k];  ix[k] = c ? 2*k+1 : 2*k;
    }
#pragma unroll
    for (int k = 0; k < 8; ++k) {
        bool c = v[2*k+1] > v[2*k];
        v[k] = c ? v[2*k+1] : v[2*k];  ix[k] = c ? ix[2*k+1] : ix[2*k];
    }
#pragma unroll
    for (int k = 0; k < 4; ++k) {
        bool c = v[2*k+1] > v[2*k];
        v[k] = c ? v[2*k+1] : v[2*k];  ix[k] = c ? ix[2*k+1] : ix[2*k];
    }
#pragma unroll
    for (int k = 0; k < 2; ++k) {
        bool c = v[2*k+1] > v[2*k];
        v[k] = c ? v[2*k+1] : v[2*k];  ix[k] = c ? ix[2*k+1] : ix[2*k];
    }
    bool c = v[1] > v[0];
    best = c ? v[1] : v[0];
    bidx = c ? ix[1] : ix[0];
}

__global__ void __launch_bounds__(64, 1)
ConstrainedDecoder_kernel(const float* __restrict__ lp,
                          const void* __restrict__ mask,
                          const void* __restrict__ startc,
                          const void* __restrict__ endc,
                          const void* __restrict__ transc,
                          float* __restrict__ out,
                          int B, int T)
{
    extern __shared__ char smem[];
    float*   buf  = (float*)smem;                         // NS * 32KB = 128KB ring
    uint8_t* back = (uint8_t*)(smem + NS * CHUNK_B);      // T * 32 bytes

    const int b   = blockIdx.x;
    const int tid = threadIdx.x;
    const int j   = tid & 31;
    const int wid = tid >> 5;

    // ---- detect bool encoding from mask[0] (guaranteed true) ----
    uint32_t w0 = ((const uint32_t*)mask)[0];
    const int mode = (w0 == 1u) ? 0 : (w0 == 0x01010101u) ? 1 : 2;

    // ---- sequence length (mask prefix-true); computed by both warps ----
    int len = 0;
    {
        const size_t mbase = (size_t)b * T;
        for (int k = j; k < T; k += 32)
            if (getb(mask, (int)(mbase + k), mode)) len = k + 1;
#pragma unroll
        for (int off = 16; off; off >>= 1)
            len = max(len, __shfl_xor_sync(FULL, len, off));
    }
    if (len < 1) len = 1;
    if (len > T) len = T;
    const int nchunk = (len + CH - 1) / CH;
    const int lenm1  = len - 1;

    if (wid == 1) {
        // =================== producer warp ===================
        const char*    g     = (const char*)(lp + (size_t)b * T * STEPF);
        const uint32_t sbase = (uint32_t)__cvta_generic_to_shared(buf);
        const size_t   limit = (size_t)T * STEPF * 4;   // bytes in this batch row

        // issue chunk cc into slot cc % NS, one commit group per chunk
        auto issue = [&](int cc) {
            size_t   goff = (size_t)cc * CHUNK_B;
            uint32_t dst  = sbase + (uint32_t)(cc & (NS - 1)) * CHUNK_B + (uint32_t)j * 16;
            const char* gs = g + goff + (size_t)j * 16;
#pragma unroll 4
            for (int r = 0; r < CHUNK_B / 512; ++r) {
                if (goff + (size_t)r * 512 + (size_t)j * 16 < limit)
                    cp16(dst + r * 512, gs + r * 512);
            }
            cp_commit();
        };

        int pre = nchunk < D ? nchunk : D;
        for (int cc = 0; cc < pre; ++cc) issue(cc);
        for (int cc = pre; cc < D; ++cc) cp_commit();   // pad to exactly D groups

        for (int c = 0; c < nchunk; ++c) {
            if (c + D < nchunk) issue(c + D); else cp_commit();
            cp_wait<D>();          // oldest group (chunk c) now complete
            barsync();             // release compute into chunk c
        }
    } else {
        // =================== compute warp ===================
        const float sp = getb(startc, j, mode) ? 0.0f : NEGINF;
        const float ep = getb(endc,   j, mode) ? 0.0f : NEGINF;
        float tp[NTAG];
#pragma unroll
        for (int i = 0; i < NTAG; ++i)
            tp[i] = getb(transc, i * NTAG + j, mode) ? 0.0f : NEGINF;

        float    my_alpha = 0.0f;
        uint8_t* bk = back + j;

        for (int c = 0; c < nchunk; ++c) {
            barsync();   // chunk c is resident
            const float* pb = buf + (size_t)(c & (NS - 1)) * CH * STEPF + j;

            int t0 = c * CH;
            int t1 = t0 + CH; if (t1 > len) t1 = len;

            if (c == 0) {
                // t = 0: alpha0[j] = max_i phi0[i][j] + sp[j] (+ ep[j] if len == 1)
                float m = pb[0];
#pragma unroll
                for (int i = 1; i < NTAG; ++i) m = fmaxf(m, pb[i * NTAG]);
                my_alpha = m + sp;
                if (len == 1) my_alpha += ep;
                t0 = 1;
            }

            int tend = t1 < lenm1 ? t1 : lenm1;   // hot steps exclude the end step
#pragma unroll 2
            for (int t = t0; t < tend; ++t) {
                const float* ph = pb + (size_t)(t & (CH - 1)) * STEPF;
                float best; int bi;
                vstep<false>(ph, tp, my_alpha, ep, best, bi);
                my_alpha = best;
                bk[(size_t)t * NTAG] = (uint8_t)bi;
            }

            if (len >= 2 && (lenm1 >> 3) == c) {
                const float* ph = pb + (size_t)(lenm1 & (CH - 1)) * STEPF;
                float best; int bi;
                vstep<true>(ph, tp, my_alpha, ep, best, bi);
                my_alpha = best;
                bk[(size_t)lenm1 * NTAG] = (uint8_t)bi;
            }
        }

        // ---- final max / first-argmax over tags ----
        __syncwarp();
        float v = my_alpha; int ix = j;
#pragma unroll
        for (int off = 16; off; off >>= 1) {
            float ov = __shfl_xor_sync(FULL, v, off);
            int   oi = __shfl_xor_sync(FULL, ix, off);
            if (ov > v || (ov == v && oi < ix)) { v = ov; ix = oi; }
        }

        float* out_mlp  = out;       // [B]
        float* out_tags = out + B;   // [B, T]
        if (j == 0) out_mlp[b] = v;

        for (int k = len + j; k < T; k += 32)
            out_tags[(size_t)b * T + k] = -1.0f;

        // ---- backtrack (lane 0, sequential smem chain) ----
        if (j == 0) {
            int tag = ix;
            out_tags[(size_t)b * T + lenm1] = (float)tag;
            for (int tt = lenm1; tt >= 1; --tt) {
                tag = back[(size_t)tt * NTAG + tag];
                out_tags[(size_t)b * T + tt - 1] = (float)tag;
            }
        }
    }
}

extern "C" void kernel_launch(void* const* d_in, const int* in_sizes, int n_in,
                              void* d_out, int out_size)
{
    const float* lp   = (const float*)d_in[0];
    const void*  mask = d_in[1];
    const void*  sc   = d_in[2];
    const void*  ec   = d_in[3];
    const void*  tc   = d_in[4];

    const int BT = in_sizes[1];      // B*T elements in mask
    int B = out_size - BT;           // out = [B] mlp + [B*T] tags
    if (B <= 0) B = 64;
    const int T = BT / B;

    size_t smem = (size_t)NS * CHUNK_B + (size_t)T * NTAG;
    cudaFuncSetAttribute(ConstrainedDecoder_kernel,
                         cudaFuncAttributeMaxDynamicSharedMemorySize, (int)smem);

    ConstrainedDecoder_kernel<<<B, 64, smem>>>(lp, mask, sc, ec, tc,
                                               (float*)d_out, B, T);
}